// round 17
// baseline (speedup 1.0000x reference)
#include <cuda_runtime.h>
#include <cstdint>

// Problem constants
#define BATCH 32
#define SEQ   4096
#define NDIM  1024
#define MROWS (BATCH * SEQ)          // 131072

// Output layout: [context (B*N)] [attn (B*S)] [coverage_out (B*S)]
#define CTX_OFF 0
#define ATT_OFF (BATCH * NDIM)                       // 32768
#define COV_OFF (BATCH * NDIM + BATCH * SEQ)         // 163840

// Scratch (static device memory; no allocation).
__device__ float g_e8[8 * MROWS];     // per-bc logit partials (BSS-zero trick)
__device__ float g_db[BATCH * NDIM];  // dec_feats + bs + bh
__device__ unsigned g_tile_ctr;       // valid-tile queue head
__device__ int g_prefix[33];          // prefix of per-batch valid row-blocks
__device__ unsigned g_total;          // total valid row-blocks

// ---------------------------------------------------------------------------
// helpers
// ---------------------------------------------------------------------------
__device__ __forceinline__ float tanh_fast(float x) {
    float r;
    asm("tanh.approx.f32 %0, %1;" : "=f"(r) : "f"(x));
    return r;
}
__device__ __forceinline__ uint32_t smem_u32(const void* p) {
    uint32_t a;
    asm("{ .reg .u64 t; cvta.to.shared.u64 t, %1; cvt.u32.u64 %0, t; }"
        : "=r"(a) : "l"(p));
    return a;
}
__device__ __forceinline__ uint32_t elect_one() {
    uint32_t p;
    asm volatile("{ .reg .pred p; elect.sync _|p, 0xFFFFFFFF; selp.b32 %0,1,0,p; }"
                 : "=r"(p));
    return p;
}
__device__ __forceinline__ void mma_tf32(float* d, const unsigned* a, const unsigned* b) {
    asm volatile(
        "mma.sync.aligned.m16n8k8.row.col.f32.tf32.tf32.f32 "
        "{%0,%1,%2,%3},{%4,%5,%6,%7},{%8,%9},{%0,%1,%2,%3};"
        : "+f"(d[0]), "+f"(d[1]), "+f"(d[2]), "+f"(d[3])
        : "r"(a[0]), "r"(a[1]), "r"(a[2]), "r"(a[3]), "r"(b[0]), "r"(b[1]));
}
#define LDSM_X4(r0, r1, r2, r3, addr) \
    asm volatile("ldmatrix.sync.aligned.m8n8.x4.shared.b16 {%0,%1,%2,%3}, [%4];" \
                 : "=r"(r0), "=r"(r1), "=r"(r2), "=r"(r3) : "r"(addr))
#define CPA16(s, g) \
    asm volatile("cp.async.cg.shared.global [%0], [%1], 16;" :: "r"(s), "l"(g))
#define MBAR_INIT(a, c) \
    asm volatile("mbarrier.init.shared.b64 [%0], %1;" :: "r"(a), "r"(c) : "memory")
#define MBAR_ARRIVE(a) \
    asm volatile("mbarrier.arrive.shared.b64 _, [%0];" :: "r"(a) : "memory")
#define CPA_MBAR_ARRIVE(a) \
    asm volatile("cp.async.mbarrier.arrive.noinc.shared::cta.b64 [%0];" \
                 :: "r"(a) : "memory")
#define MBAR_WAIT(a, ph) do {                                                  \
    uint32_t _m = (a), _p = (uint32_t)(ph), _d;                                \
    asm volatile("{\n.reg .pred p;\n"                                          \
        "mbarrier.try_wait.parity.acquire.cta.shared::cta.b64 p,[%1],%2;\n"    \
        "selp.b32 %0,1,0,p;\n}" : "=r"(_d) : "r"(_m), "r"(_p) : "memory");     \
    if (!_d) {                                                                 \
        asm volatile("{\n.reg .pred P1;\nWL%=:\n"                              \
            "mbarrier.try_wait.parity.acquire.cta.shared::cta.b64 P1,[%0],%1,0x989680;\n" \
            "@P1 bra.uni WD%=;\nbra.uni WL%=;\nWD%=:\n}"                       \
            :: "r"(_m), "r"(_p) : "memory");                                   \
    }                                                                          \
} while (0)

// ---------------------------------------------------------------------------
// 1) dec_feats + (block 0,0) valid-tile prefix table + counter reset
// ---------------------------------------------------------------------------
__global__ void dec_feats_kernel(const float* __restrict__ dec,
                                 const float* __restrict__ Ws,
                                 const float* __restrict__ bs,
                                 const float* __restrict__ bh,
                                 const int* __restrict__ lens) {
    if (blockIdx.x == 0 && blockIdx.y == 0) {
        __shared__ int nb[32];
        int t0 = threadIdx.x;
        if (t0 < 32) nb[t0] = (lens[t0] + 127) >> 7;   // row-blocks of 128
        __syncthreads();
        if (t0 < 33) {
            int p = 0;
            for (int i = 0; i < t0; i++) p += nb[i];
            g_prefix[t0] = p;
            if (t0 == 32) g_total = (unsigned)p;
        }
        if (t0 == 0) g_tile_ctr = 0u;
    }
    int b = blockIdx.x;
    int chunk = blockIdx.y;
    int w = threadIdx.x >> 5;
    int lane = threadIdx.x & 31;
    const float4* dv4 = (const float4*)(dec + b * NDIM);
#pragma unroll
    for (int j = 0; j < 4; j++) {
        int m = chunk * 32 + w * 4 + j;
        const float4* wr4 = (const float4*)(Ws + (size_t)m * NDIM);
        float s = 0.0f;
#pragma unroll
        for (int k = lane; k < NDIM / 4; k += 32) {
            float4 wv = wr4[k], dvv = dv4[k];
            s += wv.x * dvv.x + wv.y * dvv.y + wv.z * dvv.z + wv.w * dvv.w;
        }
#pragma unroll
        for (int o = 16; o > 0; o >>= 1) s += __shfl_xor_sync(0xffffffffu, s, o);
        if (lane == 0) g_db[b * NDIM + m] = s + bs[m] + bh[m];
    }
}

// ---------------------------------------------------------------------------
// 2) PERSISTENT warp-specialized GEMM.
//    384 threads: warps 0-7 = consumers (MMA, warp tile 64x32),
//                 warps 8-11 = producers (cp.async only).
//    mbarrier pipeline, NBUF=5 stages, 1 CTA/SM, 148 CTAs.
// ---------------------------------------------------------------------------
#define BM 128
#define BN 128
#define BK 32
#define NKT (NDIM / BK)   // 32
#define NBUF 5
#define LDK (BK + 4)      // 36 floats per row
#define TILE_A_F (BM * LDK)             // 4608 floats
#define TILE_B_F (BN * LDK)             // 4608 floats
#define STAGE_F (TILE_A_F + TILE_B_F)   // 9216 floats
#define STAGE_BYTES (STAGE_F * 4)       // 36864 B
#define DATA_F (NBUF * STAGE_F)         // 46080
#define SE_OFF_F   DATA_F               // s_e [128]
#define PRE_OFF_F  (DATA_F + 128)       // s_pre [33]
#define TIDX_OFF_F (DATA_F + 162)       // s_tidx [2]
#define BAR_OFF_B  ((DATA_F + 164) * 4) // 184976, 8-aligned
#define SMEM_BYTES (BAR_OFF_B + 128)
#define GEMM_CTAS 148
#define NTHR 384

__global__ __launch_bounds__(NTHR, 1)
void attn_gemm_kernel(const float* __restrict__ A,    // enc_states [M,K]
                      const float* __restrict__ Wh,   // [N,K]
                      const float* __restrict__ cov,  // [M]
                      const float* __restrict__ wc,   // [N]
                      const float* __restrict__ v,    // [N]
                      const int*   __restrict__ lens) {
    extern __shared__ float smem[];
    float* s_e = smem + SE_OFF_F;
    int* s_pre = (int*)(smem + PRE_OFF_F);
    volatile unsigned* s_tidx = (volatile unsigned*)(smem + TIDX_OFF_F);
    const uint32_t sb = smem_u32(smem);
    const uint32_t barb = sb + BAR_OFF_B;
    // barriers: stage_full[5] @0, stage_empty[5] @40, tile_full[2] @80,
    //           tile_empty[2] @96
#define STG_FULL(i)  (barb + (uint32_t)(i) * 8)
#define STG_EMPTY(i) (barb + 40u + (uint32_t)(i) * 8)
#define TIL_FULL(i)  (barb + 80u + (uint32_t)(i) * 8)
#define TIL_EMPTY(i) (barb + 96u + (uint32_t)(i) * 8)

    const int t = threadIdx.x;
    const int lane = t & 31, wid = t >> 5;

    if (t == 0) {
#pragma unroll
        for (int i = 0; i < NBUF; i++) {
            MBAR_INIT(STG_FULL(i), 128);   // producer cp-completions (.noinc)
            MBAR_INIT(STG_EMPTY(i), 8);    // consumer warp elect-arrives
        }
#pragma unroll
        for (int i = 0; i < 2; i++) {
            MBAR_INIT(TIL_FULL(i), 1);     // leader arrive
            MBAR_INIT(TIL_EMPTY(i), 12);   // all 12 warps elect-arrive
        }
    }
    if (t < 33) s_pre[t] = g_prefix[t];
    const unsigned ntv = 8u * g_total;
    __syncthreads();

    if (wid >= 8) {
        // ===================== PRODUCER WARPS ==============================
        const int ptid = t - 256;          // 0..127
        int pe_s = 0, pe_p = 1;            // stage_empty cursor (init phase 1)
        for (int k = 0;; k++) {
            const int slot = k & 1;
            const int tfp = (k >> 1) & 1;
            if (wid == 8) {
                if (elect_one()) {
                    MBAR_WAIT(TIL_EMPTY(slot), tfp ^ 1);
                    unsigned nidx = atomicAdd(&g_tile_ctr, 1u);
                    s_tidx[slot] = nidx;
                    MBAR_ARRIVE(TIL_FULL(slot));
                }
            }
            MBAR_WAIT(TIL_FULL(slot), tfp);
            const unsigned idx = s_tidx[slot];
            __syncwarp();
            if (elect_one()) MBAR_ARRIVE(TIL_EMPTY(slot));
            if (idx >= ntv) return;

            const int bc = idx & 7;
            const int vt = (int)(idx >> 3);
            int cond = (vt >= s_pre[lane]) && (vt < s_pre[lane + 1]);
            unsigned mask = __ballot_sync(0xffffffffu, cond);
            const int b = __ffs(mask) - 1;
            const int br = b * 32 + (vt - s_pre[b]);
            const float* Ablk = A  + (size_t)br * BM * NDIM;
            const float* Bblk = Wh + (size_t)bc * BN * NDIM;

            for (int s = 0; s < NKT; ++s) {
                MBAR_WAIT(STG_EMPTY(pe_s), pe_p);
                const uint32_t ab = sb + (uint32_t)pe_s * STAGE_BYTES;
                const uint32_t bb = ab + TILE_A_F * 4;
                const int k0 = s * BK;
#pragma unroll
                for (int i = 0; i < 8; i++) {     // A: 1024 chunks / 128 thr
                    int c = ptid + i * 128;
                    int r = c >> 3, ch = c & 7;
                    CPA16(ab + (uint32_t)(r * LDK + ch * 4) * 4,
                          Ablk + (size_t)r * NDIM + k0 + ch * 4);
                }
#pragma unroll
                for (int i = 0; i < 8; i++) {     // B: 1024 chunks / 128 thr
                    int c = ptid + i * 128;
                    int r = c >> 3, ch = c & 7;
                    CPA16(bb + (uint32_t)(r * LDK + ch * 4) * 4,
                          Bblk + (size_t)r * NDIM + k0 + ch * 4);
                }
                CPA_MBAR_ARRIVE(STG_FULL(pe_s));
                if (++pe_s == NBUF) { pe_s = 0; pe_p ^= 1; }
            }
        }
    } else {
        // ===================== CONSUMER WARPS ==============================
        const int warp_m = wid >> 2, warp_n = wid & 3;   // 2 x 4
        const int g = lane >> 2, tig = lane & 3;

        uint32_t a_off[4];
#pragma unroll
        for (int mt = 0; mt < 4; mt++) {
            int row = warp_m * 64 + mt * 16 + (lane & 15);
            int kc  = (lane >> 4) * 4;
            a_off[mt] = (uint32_t)(row * LDK + kc) * 4;
        }
        uint32_t b_off[2];
#pragma unroll
        for (int p = 0; p < 2; p++) {
            int nrow = warp_n * 32 + p * 16 + (lane & 7) + ((lane >> 4) & 1) * 8;
            int kc   = ((lane >> 3) & 1) * 4;
            b_off[p] = (uint32_t)(TILE_A_F * 4) + (uint32_t)(nrow * LDK + kc) * 4;
        }

#define DO_KK(kk_ofs)                                                          \
    do {                                                                       \
        unsigned af[4][4], bf[4][2];                                           \
        _Pragma("unroll")                                                      \
        for (int mt = 0; mt < 4; mt++)                                         \
            LDSM_X4(af[mt][0], af[mt][1], af[mt][2], af[mt][3],                \
                    (kk_ofs) + a_off[mt]);                                     \
        _Pragma("unroll")                                                      \
        for (int p = 0; p < 2; p++)                                            \
            LDSM_X4(bf[2 * p][0], bf[2 * p][1], bf[2 * p + 1][0],              \
                    bf[2 * p + 1][1], (kk_ofs) + b_off[p]);                    \
        _Pragma("unroll")                                                      \
        for (int mt = 0; mt < 4; mt++)                                         \
            _Pragma("unroll")                                                  \
            for (int nt = 0; nt < 4; nt++)                                     \
                mma_tf32(acc[mt][nt], af[mt], bf[nt]);                         \
    } while (0)

        int cf_s = 0, cf_p = 0;            // stage_full cursor
        for (int k = 0;; k++) {
            const int slot = k & 1;
            const int tfp = (k >> 1) & 1;
            MBAR_WAIT(TIL_FULL(slot), tfp);
            const unsigned idx = s_tidx[slot];
            __syncwarp();
            if (elect_one()) MBAR_ARRIVE(TIL_EMPTY(slot));
            if (idx >= ntv) return;

            const int bc = idx & 7;
            const int vt = (int)(idx >> 3);
            int cond = (vt >= s_pre[lane]) && (vt < s_pre[lane + 1]);
            unsigned mask = __ballot_sync(0xffffffffu, cond);
            const int b = __ffs(mask) - 1;
            const int br = b * 32 + (vt - s_pre[b]);

            if (t < BM) s_e[t] = 0.0f;     // safe: bar1 after prev g_e8 store
            asm volatile("bar.sync 1, 256;" ::: "memory");

            float acc[4][4][4];
#pragma unroll
            for (int i = 0; i < 4; i++)
#pragma unroll
                for (int j = 0; j < 4; j++)
#pragma unroll
                    for (int kk = 0; kk < 4; kk++) acc[i][j][kk] = 0.0f;

            for (int s = 0; s < NKT; ++s) {
                MBAR_WAIT(STG_FULL(cf_s), cf_p);
                const uint32_t cur = sb + (uint32_t)cf_s * STAGE_BYTES;
                DO_KK(cur);
                DO_KK(cur + 32);
                DO_KK(cur + 64);
                DO_KK(cur + 96);
                __syncwarp();
                if (elect_one()) MBAR_ARRIVE(STG_EMPTY(cf_s));
                if (++cf_s == NBUF) { cf_s = 0; cf_p ^= 1; }
            }

            // fused epilogue: tanh + dot with v, reduce over columns
            float vv[4][2], ww[4][2], dd[4][2];
#pragma unroll
            for (int nt = 0; nt < 4; nt++)
#pragma unroll
                for (int j = 0; j < 2; j++) {
                    int col = bc * BN + warp_n * 32 + nt * 8 + 2 * tig + j;
                    vv[nt][j] = v[col];
                    ww[nt][j] = wc[col];
                    dd[nt][j] = g_db[b * NDIM + col];
                }

#pragma unroll
            for (int mt = 0; mt < 4; mt++) {
#pragma unroll
                for (int h = 0; h < 2; h++) {
                    int rl = warp_m * 64 + mt * 16 + g + 8 * h;
                    size_t rg = (size_t)br * BM + rl;
                    float cv = cov[rg];
                    float sum = 0.0f;
#pragma unroll
                    for (int nt = 0; nt < 4; nt++)
#pragma unroll
                        for (int j = 0; j < 2; j++) {
                            float x = acc[mt][nt][2 * h + j] + dd[nt][j] +
                                      cv * ww[nt][j];
                            sum += vv[nt][j] * tanh_fast(x);
                        }
                    sum += __shfl_xor_sync(0xffffffffu, sum, 1);
                    sum += __shfl_xor_sync(0xffffffffu, sum, 2);
                    if (tig == 0) atomicAdd(&s_e[rl], sum);
                }
            }
            asm volatile("bar.sync 1, 256;" ::: "memory");
            if (t < BM) g_e8[(size_t)bc * MROWS + (size_t)br * BM + t] = s_e[t];
        }
#undef DO_KK
    }
}

// ---------------------------------------------------------------------------
// 3) masked renormalized softmax per batch row + coverage_out (+ ctx zeroing)
// ---------------------------------------------------------------------------
__global__ void softmax_kernel(const float* __restrict__ cov,
                               const int* __restrict__ lens,
                               float* __restrict__ out) {
    const int b = blockIdx.x;
    const int t = threadIdx.x;  // 256
    __shared__ float red[256];
    const int len = lens[b];

#pragma unroll
    for (int i = 0; i < NDIM / 256; i++)
        out[CTX_OFF + b * NDIM + i * 256 + t] = 0.0f;

    float ev[16];
    float lmax = -1e30f;
#pragma unroll
    for (int i = 0; i < 16; i++) {
        int s = t + i * 256;
        size_t idx = (size_t)b * SEQ + s;
        float e = 0.0f;
#pragma unroll
        for (int p = 0; p < 8; p++) e += g_e8[(size_t)p * MROWS + idx];
        ev[i] = e;
        if (s < len) lmax = fmaxf(lmax, e);
    }
    red[t] = lmax;
    __syncthreads();
    for (int o = 128; o > 0; o >>= 1) {
        if (t < o) red[t] = fmaxf(red[t], red[t + o]);
        __syncthreads();
    }
    float m = red[0];
    __syncthreads();

    float lsum = 0.0f;
#pragma unroll
    for (int i = 0; i < 16; i++) {
        int s = t + i * 256;
        float x = (s < len) ? __expf(ev[i] - m) : 0.0f;
        ev[i] = x;
        lsum += x;
    }
    red[t] = lsum;
    __syncthreads();
    for (int o = 128; o > 0; o >>= 1) {
        if (t < o) red[t] += red[t + o];
        __syncthreads();
    }
    float inv = 1.0f / red[0];

#pragma unroll
    for (int i = 0; i < 16; i++) {
        int s = t + i * 256;
        float a = ev[i] * inv;
        out[ATT_OFF + b * SEQ + s] = a;
        out[COV_OFF + b * SEQ + s] = cov[b * SEQ + s] + a;
    }
}

// ---------------------------------------------------------------------------
// 4) context[b] = sum_s attn[b,s] * enc[b,s,:]  — 64-row chunks, skip zeros
// ---------------------------------------------------------------------------
__global__ void context_kernel(const float* __restrict__ enc,
                               const float* __restrict__ out_attn,
                               float* __restrict__ ctx) {
    const int b = blockIdx.x;
    const int sc = blockIdx.y;          // 0..63, 64 rows each
    const int t = threadIdx.x;          // 256
    __shared__ float sa[64];
    if (t < 64) sa[t] = out_attn[b * SEQ + sc * 64 + t];
    int any = __syncthreads_or((t < 64) ? (sa[t] != 0.0f) : 0);
    if (!any) return;

    const float4* base =
        (const float4*)(enc + ((size_t)b * SEQ + sc * 64) * NDIM);
    float4 acc = make_float4(0.f, 0.f, 0.f, 0.f);
#pragma unroll 4
    for (int s = 0; s < 64; s++) {
        float a = sa[s];
        float4 x = base[s * 256 + t];
        acc.x += a * x.x;
        acc.y += a * x.y;
        acc.z += a * x.z;
        acc.w += a * x.w;
    }
    float* c = ctx + b * NDIM + t * 4;
    atomicAdd(c + 0, acc.x);
    atomicAdd(c + 1, acc.y);
    atomicAdd(c + 2, acc.z);
    atomicAdd(c + 3, acc.w);
}

// ---------------------------------------------------------------------------
// launch
// ---------------------------------------------------------------------------
extern "C" void kernel_launch(void* const* d_in, const int* in_sizes, int n_in,
                              void* d_out, int out_size) {
    const float* dec  = (const float*)d_in[0];  // [B,N]
    const float* enc  = (const float*)d_in[1];  // [B,S,N]
    const int*   lens = (const int*)  d_in[2];  // [B]
    const float* cov  = (const float*)d_in[3];  // [B,S]
    const float* Wh   = (const float*)d_in[4];  // [N,N]
    const float* bh   = (const float*)d_in[5];  // [N]
    const float* Ws   = (const float*)d_in[6];  // [N,N]
    const float* bs   = (const float*)d_in[7];  // [N]
    const float* wc   = (const float*)d_in[8];  // [N]
    const float* v    = (const float*)d_in[9];  // [N]
    float* out = (float*)d_out;

    cudaFuncSetAttribute(attn_gemm_kernel,
                         cudaFuncAttributeMaxDynamicSharedMemorySize, SMEM_BYTES);

    dec_feats_kernel<<<dim3(BATCH, 32), 256>>>(dec, Ws, bs, bh, lens);
    attn_gemm_kernel<<<GEMM_CTAS, NTHR, SMEM_BYTES>>>(enc, Wh, cov, wc, v, lens);
    softmax_kernel<<<BATCH, 256>>>(cov, lens, out);
    context_kernel<<<dim3(BATCH, SEQ / 64), 256>>>(enc, out + ATT_OFF, out + CTX_OFF);
}